// round 2
// baseline (speedup 1.0000x reference)
#include <cuda_runtime.h>
#include <math.h>

// Problem dims
#define Bc  32
#define Tc  128
#define TYc 64
#define Ec  512
#define Hc  512
#define HHc 256
#define Vc  32000

// ---------------- scratch (__device__ globals; no allocations) ----------------
__device__ float g_xemb  [Bc*Tc*Ec];
__device__ float g_xbemb [Bc*Tc*Ec];
__device__ float g_yemb  [Bc*TYc*Ec];
__device__ int   g_xback [Bc*Tc];
__device__ float g_encpre_f[Bc*Tc*4*HHc];
__device__ float g_encpre_b[Bc*Tc*4*HHc];
__device__ float g_decpre  [Bc*TYc*4*Hc];
__device__ float g_ench[2][2*Bc*HHc];   // ping-pong h state, [dir][b][u]
__device__ float g_encc[2*Bc*HHc];      // c state, in-place
__device__ float g_hiddens[Bc*Tc*Hc];   // [b][t][fwd|bwd]
__device__ float g_hsum[Bc*Hc];
__device__ float g_csum[Bc*Hc];
__device__ float g_dech[2][Bc*Hc];      // ping-pong decoder h
__device__ float g_decc[Bc*Hc];
__device__ float g_outhid[Bc*TYc*2*Hc]; // [b][ty][h|ctx]

__device__ __forceinline__ float sigm(float x) { return 1.f / (1.f + expf(-x)); }

// ---------------- init ----------------
__global__ void k_init() {
    int i = blockIdx.x * blockDim.x + threadIdx.x;
    if (i < Bc*Hc)      { g_hsum[i] = 0.f; g_csum[i] = 0.f; }
    if (i < 2*2*Bc*HHc) (&g_ench[0][0])[i] = 0.f;
    if (i < 2*Bc*HHc)   g_encc[i] = 0.f;
    if (i < Bc*Tc)      g_xback[i] = 0;
}

// ---------------- pad-aware reversed tokens ----------------
__global__ void k_xback(const int* __restrict__ x, const float* __restrict__ mask) {
    int b = threadIdx.x;
    if (b >= Bc) return;
    float s = 0.f;
    for (int t = 0; t < Tc; t++) s += mask[b*Tc + t];
    int pad = Tc - (int)(s + 0.5f);
    for (int j = 0; j < Tc; j++) {           // ascending j: later writes win (matches scatter order)
        int r = Tc - 1 - j - pad;
        if (r < 0) r = 0;
        g_xback[b*Tc + r] = x[b*Tc + j];
    }
}

// ---------------- embedding gather (one block per row, E/4 float4s) ----------------
__global__ void k_gather(const int* __restrict__ idx, const float* __restrict__ embed,
                         float* __restrict__ out) {
    int row = blockIdx.x;
    int e = threadIdx.x;                     // 128 threads
    const float4* src = (const float4*)embed + (size_t)idx[row] * (Ec/4);
    ((float4*)out)[(size_t)row * (Ec/4) + e] = src[e];
}

// ---------------- SGEMM: C[M,N] = A[M,K] @ W[N,K]^T (+b1[n] +b2[n]) ----------------
// 128x128 tile, BK=8, 256 threads, 8x8 per thread. All dims multiples of tile.
__global__ __launch_bounds__(256, 2)
void k_sgemm(const float* __restrict__ A, const float* __restrict__ Wt,
             const float* __restrict__ b1, const float* __restrict__ b2,
             float* __restrict__ C, int M, int N, int K) {
    __shared__ float As[8][128];
    __shared__ float Ws[8][128];
    const int tid = threadIdx.x;
    const int bm = blockIdx.y * 128;
    const int bn = blockIdx.x * 128;
    const int lr = tid >> 1;
    const int lk = (tid & 1) * 4;
    const int tx = tid & 15;
    const int ty = tid >> 4;
    const float* Ap = A  + (size_t)(bm + lr) * K + lk;
    const float* Wp = Wt + (size_t)(bn + lr) * K + lk;
    float acc[8][8];
#pragma unroll
    for (int i = 0; i < 8; i++)
#pragma unroll
        for (int j = 0; j < 8; j++) acc[i][j] = 0.f;

    for (int k0 = 0; k0 < K; k0 += 8) {
        float4 av = *(const float4*)(Ap + k0);
        float4 wv = *(const float4*)(Wp + k0);
        As[lk+0][lr] = av.x; As[lk+1][lr] = av.y; As[lk+2][lr] = av.z; As[lk+3][lr] = av.w;
        Ws[lk+0][lr] = wv.x; Ws[lk+1][lr] = wv.y; Ws[lk+2][lr] = wv.z; Ws[lk+3][lr] = wv.w;
        __syncthreads();
#pragma unroll
        for (int kk = 0; kk < 8; kk++) {
            float a[8], w[8];
            *(float4*)(a)     = *(const float4*)&As[kk][ty*8];
            *(float4*)(a + 4) = *(const float4*)&As[kk][ty*8 + 4];
            *(float4*)(w)     = *(const float4*)&Ws[kk][tx*8];
            *(float4*)(w + 4) = *(const float4*)&Ws[kk][tx*8 + 4];
#pragma unroll
            for (int i = 0; i < 8; i++)
#pragma unroll
                for (int j = 0; j < 8; j++) acc[i][j] += a[i] * w[j];
        }
        __syncthreads();
    }
#pragma unroll
    for (int i = 0; i < 8; i++) {
        int row = bm + ty*8 + i;
        float* crow = C + (size_t)row * N + bn + tx*8;
#pragma unroll
        for (int j = 0; j < 8; j++) {
            int n = bn + tx*8 + j;
            float v = acc[i][j];
            if (b1) v += b1[n];
            if (b2) v += b2[n];
            crow[j] = v;
        }
    }
}

// ---------------- encoder step (both directions, one launch per t) ----------------
// grid (HH/8, 2), 256 threads. Block: 8 hidden units x 4 gates x 32 batches.
__global__ __launch_bounds__(256, 1)
void k_enc_step(int t, const float* __restrict__ whh_f, const float* __restrict__ whh_b) {
    const int dir = blockIdx.y;
    const int u0 = blockIdx.x * 8;
    const float* whh = dir ? whh_b : whh_f;
    const float* pre = dir ? g_encpre_b : g_encpre_f;
    float* cst = g_encc + dir * (Bc*HHc);
    const float* h_in = g_ench[t & 1] + dir * (Bc*HHc);
    float* h_out = g_ench[(t + 1) & 1] + dir * (Bc*HHc);

    __shared__ float sh[HHc * 36];           // h transposed [k][b] (pad 36), reused for gates
    for (int j = threadIdx.x; j < Bc*HHc; j += 256) {
        int k = j >> 5, b = j & 31;
        sh[k*36 + b] = h_in[b*HHc + k];
    }
    __syncthreads();

    const int col = threadIdx.x >> 3;        // 0..31 : gate-col within block
    const int b0  = (threadIdx.x & 7) * 4;   // 4 batches per thread
    const int gg = col >> 3, uu = col & 7;
    const int gcol = gg*HHc + u0 + uu;
    const float* wrow = whh + (size_t)gcol * HHc;
    float a0 = 0.f, a1 = 0.f, a2 = 0.f, a3 = 0.f;
#pragma unroll 4
    for (int k = 0; k < HHc; k += 4) {
        float4 w4 = *(const float4*)(wrow + k);
        float4 h0 = *(const float4*)&sh[(k+0)*36 + b0];
        float4 h1 = *(const float4*)&sh[(k+1)*36 + b0];
        float4 h2 = *(const float4*)&sh[(k+2)*36 + b0];
        float4 h3 = *(const float4*)&sh[(k+3)*36 + b0];
        a0 += w4.x*h0.x + w4.y*h1.x + w4.z*h2.x + w4.w*h3.x;
        a1 += w4.x*h0.y + w4.y*h1.y + w4.z*h2.y + w4.w*h3.y;
        a2 += w4.x*h0.z + w4.y*h1.z + w4.z*h2.z + w4.w*h3.z;
        a3 += w4.x*h0.w + w4.y*h1.w + w4.z*h2.w + w4.w*h3.w;
    }
    __syncthreads();
    sh[col*33 + b0 + 0] = a0;
    sh[col*33 + b0 + 1] = a1;
    sh[col*33 + b0 + 2] = a2;
    sh[col*33 + b0 + 3] = a3;
    __syncthreads();

    // cell update: one (b, unit) per thread
    const int b  = threadIdx.x & 31;
    const int u2 = threadIdx.x >> 5;         // 0..7
    const int u  = u0 + u2;
    const float* prebt = pre + (size_t)(b*Tc + t) * (4*HHc);
    float gi = sh[(0*8 + u2)*33 + b] + prebt[0*HHc + u];
    float gf = sh[(1*8 + u2)*33 + b] + prebt[1*HHc + u];
    float gc = sh[(2*8 + u2)*33 + b] + prebt[2*HHc + u];
    float go = sh[(3*8 + u2)*33 + b] + prebt[3*HHc + u];
    float cold = cst[b*HHc + u];
    float cnew = sigm(gf) * cold + sigm(gi) * tanhf(gc);
    float hnew = sigm(go) * tanhf(cnew);
    cst[b*HHc + u] = cnew;
    h_out[b*HHc + u] = hnew;
    g_hiddens[(size_t)(b*Tc + t)*Hc + dir*HHc + u] = hnew;
    g_hsum[b*Hc + dir*HHc + u] += hnew;
    g_csum[b*Hc + dir*HHc + u] += cnew;
}

// ---------------- mean over T -> decoder initial state ----------------
__global__ void k_mean() {
    int i = blockIdx.x * blockDim.x + threadIdx.x;
    if (i < Bc*Hc) {
        g_dech[0][i] = g_hsum[i] * (1.0f / Tc);
        g_decc[i]    = g_csum[i] * (1.0f / Tc);
    }
}

// ---------------- decoder LSTM step (one launch per ty) ----------------
// grid H/8 = 64 blocks, 256 threads. K=512 chunked 2x256 through smem.
__global__ __launch_bounds__(256, 1)
void k_dec_step(int ty, const float* __restrict__ whh) {
    const int u0 = blockIdx.x * 8;
    const float* h_in = g_dech[ty & 1];
    float* h_out = g_dech[(ty + 1) & 1];
    __shared__ float sh[256 * 36];

    const int col = threadIdx.x >> 3;
    const int b0  = (threadIdx.x & 7) * 4;
    const int gg = col >> 3, uu = col & 7;
    const int gcol = gg*Hc + u0 + uu;
    const float* wrow = whh + (size_t)gcol * Hc;
    float a0 = 0.f, a1 = 0.f, a2 = 0.f, a3 = 0.f;

    for (int kc = 0; kc < Hc; kc += 256) {
        for (int j = threadIdx.x; j < Bc*256; j += 256) {
            int k = j >> 5, bb = j & 31;
            sh[k*36 + bb] = h_in[bb*Hc + kc + k];
        }
        __syncthreads();
#pragma unroll 4
        for (int k = 0; k < 256; k += 4) {
            float4 w4 = *(const float4*)(wrow + kc + k);
            float4 h0 = *(const float4*)&sh[(k+0)*36 + b0];
            float4 h1 = *(const float4*)&sh[(k+1)*36 + b0];
            float4 h2 = *(const float4*)&sh[(k+2)*36 + b0];
            float4 h3 = *(const float4*)&sh[(k+3)*36 + b0];
            a0 += w4.x*h0.x + w4.y*h1.x + w4.z*h2.x + w4.w*h3.x;
            a1 += w4.x*h0.y + w4.y*h1.y + w4.z*h2.y + w4.w*h3.y;
            a2 += w4.x*h0.z + w4.y*h1.z + w4.z*h2.z + w4.w*h3.z;
            a3 += w4.x*h0.w + w4.y*h1.w + w4.z*h2.w + w4.w*h3.w;
        }
        __syncthreads();
    }
    sh[col*33 + b0 + 0] = a0;
    sh[col*33 + b0 + 1] = a1;
    sh[col*33 + b0 + 2] = a2;
    sh[col*33 + b0 + 3] = a3;
    __syncthreads();

    const int b  = threadIdx.x & 31;
    const int u2 = threadIdx.x >> 5;
    const int u  = u0 + u2;
    const float* prebt = g_decpre + (size_t)(b*TYc + ty) * (4*Hc);
    float gi = sh[(0*8 + u2)*33 + b] + prebt[0*Hc + u];
    float gf = sh[(1*8 + u2)*33 + b] + prebt[1*Hc + u];
    float gc = sh[(2*8 + u2)*33 + b] + prebt[2*Hc + u];
    float go = sh[(3*8 + u2)*33 + b] + prebt[3*Hc + u];
    float cold = g_decc[b*Hc + u];
    float cnew = sigm(gf) * cold + sigm(gi) * tanhf(gc);
    float hnew = sigm(go) * tanhf(cnew);
    g_decc[b*Hc + u] = cnew;
    h_out[b*Hc + u] = hnew;
    g_outhid[(size_t)(b*TYc + ty)*(2*Hc) + u] = hnew;
}

// ---------------- attention (one block per batch, per ty) ----------------
__global__ __launch_bounds__(256, 1)
void k_dec_attn(int ty) {
    const int b = blockIdx.x;
    const float* h = g_dech[(ty + 1) & 1] + b*Hc;
    __shared__ float hs[Hc];
    __shared__ float sc[Tc];
    __shared__ float red[8];
    for (int i = threadIdx.x; i < Hc; i += 256) hs[i] = h[i];
    __syncthreads();

    // scores: 2 threads per t', 256-elem half dot each
    const int tp = threadIdx.x >> 1;
    const int half = threadIdx.x & 1;
    const float* hid = g_hiddens + (size_t)(b*Tc + tp)*Hc + half*256;
    const float* hq = hs + half*256;
    float s = 0.f;
#pragma unroll 4
    for (int k = 0; k < 256; k += 4) {
        float4 a = *(const float4*)(hid + k);
        float4 c = *(const float4*)(hq + k);
        s += a.x*c.x + a.y*c.y + a.z*c.z + a.w*c.w;
    }
    s += __shfl_down_sync(0xffffffffu, s, 1);
    if (half == 0) sc[tp] = s;
    __syncthreads();

    // softmax over T=128
    const int lane = threadIdx.x & 31, wid = threadIdx.x >> 5;
    float v = (threadIdx.x < Tc) ? sc[threadIdx.x] : -1e30f;
    float m = v;
    for (int o = 16; o; o >>= 1) m = fmaxf(m, __shfl_xor_sync(0xffffffffu, m, o));
    if (!lane) red[wid] = m;
    __syncthreads();
    if (!wid) {
        float xx = (lane < 8) ? red[lane] : -1e30f;
        for (int o = 4; o; o >>= 1) xx = fmaxf(xx, __shfl_xor_sync(0xffffffffu, xx, o));
        if (!lane) red[0] = xx;
    }
    __syncthreads();
    m = red[0];
    float e = (threadIdx.x < Tc) ? expf(v - m) : 0.f;
    float ssum = e;
    for (int o = 16; o; o >>= 1) ssum += __shfl_xor_sync(0xffffffffu, ssum, o);
    __syncthreads();
    if (!lane) red[wid] = ssum;
    __syncthreads();
    if (!wid) {
        float xx = (lane < 8) ? red[lane] : 0.f;
        for (int o = 4; o; o >>= 1) xx += __shfl_xor_sync(0xffffffffu, xx, o);
        if (!lane) red[0] = xx;
    }
    __syncthreads();
    float inv = 1.f / red[0];
    if (threadIdx.x < Tc) sc[threadIdx.x] = e * inv;
    __syncthreads();

    // context
    float* octx = g_outhid + (size_t)(b*TYc + ty)*(2*Hc) + Hc;
    for (int d = threadIdx.x; d < Hc; d += 256) {
        float a = 0.f;
#pragma unroll 8
        for (int tq = 0; tq < Tc; tq++) a += sc[tq] * g_hiddens[(size_t)(b*Tc + tq)*Hc + d];
        octx[d] = a;
    }
}

// ---------------- in-place log_softmax over rows of V ----------------
__global__ __launch_bounds__(256)
void k_logsoftmax(float* __restrict__ out) {
    const int row = blockIdx.x;
    float* p = out + (size_t)row * Vc;
    __shared__ float red[8];
    const int lane = threadIdx.x & 31, wid = threadIdx.x >> 5;
    float m = -1e30f;
    for (int i = threadIdx.x; i < Vc; i += 256) m = fmaxf(m, p[i]);
    for (int o = 16; o; o >>= 1) m = fmaxf(m, __shfl_xor_sync(0xffffffffu, m, o));
    if (!lane) red[wid] = m;
    __syncthreads();
    if (!wid) {
        float xx = (lane < 8) ? red[lane] : -1e30f;
        for (int o = 4; o; o >>= 1) xx = fmaxf(xx, __shfl_xor_sync(0xffffffffu, xx, o));
        if (!lane) red[0] = xx;
    }
    __syncthreads();
    m = red[0];
    float s = 0.f;
    for (int i = threadIdx.x; i < Vc; i += 256) s += expf(p[i] - m);
    for (int o = 16; o; o >>= 1) s += __shfl_xor_sync(0xffffffffu, s, o);
    __syncthreads();
    if (!lane) red[wid] = s;
    __syncthreads();
    if (!wid) {
        float xx = (lane < 8) ? red[lane] : 0.f;
        for (int o = 4; o; o >>= 1) xx += __shfl_xor_sync(0xffffffffu, xx, o);
        if (!lane) red[0] = xx;
    }
    __syncthreads();
    float lse = m + logf(red[0]);
    for (int i = threadIdx.x; i < Vc; i += 256) p[i] -= lse;
}

__global__ void k_copy_tail(float* __restrict__ dst) {
    int i = blockIdx.x * blockDim.x + threadIdx.x;
    if (i < Bc*TYc*2*Hc) dst[i] = g_outhid[i];
}

// ---------------- launch ----------------
extern "C" void kernel_launch(void* const* d_in, const int* in_sizes, int n_in,
                              void* d_out, int out_size) {
    (void)in_sizes; (void)n_in;
    const int*   x      = (const int*)  d_in[0];
    const float* xmask  = (const float*)d_in[1];
    const int*   y      = (const int*)  d_in[2];
    const float* embed  = (const float*)d_in[3];
    const float* w_ih_f = (const float*)d_in[4];
    const float* w_hh_f = (const float*)d_in[5];
    const float* b_ih_f = (const float*)d_in[6];
    const float* b_hh_f = (const float*)d_in[7];
    const float* w_ih_b = (const float*)d_in[8];
    const float* w_hh_b = (const float*)d_in[9];
    const float* b_ih_b = (const float*)d_in[10];
    const float* b_hh_b = (const float*)d_in[11];
    const float* w_ih_d = (const float*)d_in[12];
    const float* w_hh_d = (const float*)d_in[13];
    const float* b_ih_d = (const float*)d_in[14];
    const float* b_hh_d = (const float*)d_in[15];
    const float* W_out  = (const float*)d_in[16];
    const float* b_out  = (const float*)d_in[17];
    float* out = (float*)d_out;

    void *p_xemb, *p_xbemb, *p_yemb, *p_pref, *p_preb, *p_decpre, *p_outhid, *p_xback;
    cudaGetSymbolAddress(&p_xemb,   g_xemb);
    cudaGetSymbolAddress(&p_xbemb,  g_xbemb);
    cudaGetSymbolAddress(&p_yemb,   g_yemb);
    cudaGetSymbolAddress(&p_pref,   g_encpre_f);
    cudaGetSymbolAddress(&p_preb,   g_encpre_b);
    cudaGetSymbolAddress(&p_decpre, g_decpre);
    cudaGetSymbolAddress(&p_outhid, g_outhid);
    cudaGetSymbolAddress(&p_xback,  g_xback);

    k_init<<<128, 256>>>();
    k_xback<<<1, 32>>>(x, xmask);
    k_gather<<<Bc*Tc, 128>>>(x, embed, (float*)p_xemb);
    k_gather<<<Bc*Tc, 128>>>((const int*)p_xback, embed, (float*)p_xbemb);
    k_gather<<<Bc*TYc, 128>>>(y, embed, (float*)p_yemb);

    // time-batched input-side GEMMs (fold both biases)
    k_sgemm<<<dim3((4*HHc)/128, (Bc*Tc)/128), 256>>>((const float*)p_xemb,  w_ih_f, b_ih_f, b_hh_f, (float*)p_pref,   Bc*Tc,  4*HHc, Ec);
    k_sgemm<<<dim3((4*HHc)/128, (Bc*Tc)/128), 256>>>((const float*)p_xbemb, w_ih_b, b_ih_b, b_hh_b, (float*)p_preb,   Bc*Tc,  4*HHc, Ec);
    k_sgemm<<<dim3((4*Hc)/128,  (Bc*TYc)/128), 256>>>((const float*)p_yemb, w_ih_d, b_ih_d, b_hh_d, (float*)p_decpre, Bc*TYc, 4*Hc,  Ec);

    for (int t = 0; t < Tc; t++)
        k_enc_step<<<dim3(HHc/8, 2), 256>>>(t, w_hh_f, w_hh_b);

    k_mean<<<(Bc*Hc + 255)/256, 256>>>();

    for (int ty = 0; ty < TYc; ty++) {
        k_dec_step<<<Hc/8, 256>>>(ty, w_hh_d);
        k_dec_attn<<<Bc, 256>>>(ty);
    }

    // projection: logits straight into d_out, then in-place log_softmax
    k_sgemm<<<dim3(Vc/128, (Bc*TYc)/128), 256>>>((const float*)p_outhid, W_out, b_out, nullptr, out, Bc*TYc, Vc, 2*Hc);
    k_logsoftmax<<<Bc*TYc, 256>>>(out);

    long long need = (long long)Bc*TYc*Vc + (long long)Bc*TYc*2*Hc;
    if ((long long)out_size >= need)
        k_copy_tail<<<(Bc*TYc*2*Hc + 255)/256, 256>>>(out + (size_t)Bc*TYc*Vc);
}